// round 8
// baseline (speedup 1.0000x reference)
#include <cuda_runtime.h>
#include <cuda_bf16.h>
#include <cstdint>

// Problem constants (fixed by the reference: S=64, C=32)
#define SPATIAL 64
#define KEY_SPACE (SPATIAL * SPATIAL * SPATIAL * SPATIAL)  // 16,777,216
#define NWORDS (KEY_SPACE / 32)                            // 524,288
#define NBLOCKS_SCAN 512                                   // NWORDS / 1024
#define MAXN (1 << 21)

// Scratch (device globals — no allocation allowed)
__device__ unsigned g_bitmap[NWORDS];      // presence bits
__device__ unsigned g_dup[NWORDS];         // duplicate-key bits
__device__ unsigned g_wordPrefix[NWORDS];  // exclusive prefix of popcounts
__device__ unsigned long long g_scanState[NBLOCKS_SCAN];  // (sum<<32)|flag
__device__ unsigned g_keys[MAXN];
__device__ unsigned g_numUnique;

// ---------------------------------------------------------------------------
// 1) zero bitmaps + lookback state (R3-proven)
__global__ void k_init() {
    int i = blockIdx.x * blockDim.x + threadIdx.x;
    uint4 z = make_uint4(0, 0, 0, 0);
    if (i < NWORDS / 4)                ((uint4*)g_bitmap)[i] = z;
    else if (i < 2 * (NWORDS / 4))     ((uint4*)g_dup)[i - NWORDS / 4] = z;
    else if (i < 2 * (NWORDS / 4) + NBLOCKS_SCAN / 2)
        ((uint4*)g_scanState)[i - 2 * (NWORDS / 4)] = z;
}

// ---------------------------------------------------------------------------
// 2) presence + dup bitmaps, key cache — 1 point/thread (R3-proven; LSU-floor bound)
__global__ void k_build(const int4* __restrict__ coords, int n) {
    int i = blockIdx.x * blockDim.x + threadIdx.x;
    if (i >= n) return;
    int4 c = coords[i];
    unsigned key = ((unsigned)((c.x * SPATIAL + c.y) * SPATIAL + c.z)) * SPATIAL + (unsigned)c.w;
    g_keys[i] = key;
    unsigned bit = 1u << (key & 31);
    unsigned old = atomicOr(&g_bitmap[key >> 5], bit);
    if (old & bit) atomicOr(&g_dup[key >> 5], bit);
}

// ---------------------------------------------------------------------------
// 3) single-pass scan (decoupled lookback) + inline dup-row zeroing (R3-proven)
__global__ void __launch_bounds__(256) k_scan_fused(float4* __restrict__ out) {
    int blk = blockIdx.x, t = threadIdx.x;
    uint4 v = ((const uint4*)g_bitmap)[blk * 256 + t];
    unsigned c0 = __popc(v.x), c1 = __popc(v.y), c2 = __popc(v.z), c3 = __popc(v.w);
    unsigned local = c0 + c1 + c2 + c3;

    unsigned inc = local;
#pragma unroll
    for (int o = 1; o < 32; o <<= 1) {
        unsigned nv = __shfl_up_sync(0xffffffffu, inc, o);
        if ((t & 31) >= o) inc += nv;
    }
    __shared__ unsigned ws[8];
    __shared__ unsigned sh_total, sh_excl;
    if ((t & 31) == 31) ws[t >> 5] = inc;
    __syncthreads();
    if (t < 8) {
        unsigned x = ws[t], xi = x;
#pragma unroll
        for (int o = 1; o < 8; o <<= 1) {
            unsigned nv = __shfl_up_sync(0xffu, xi, o);
            if (t >= o) xi += nv;
        }
        ws[t] = xi - x;
        if (t == 7) sh_total = xi;
    }
    __syncthreads();
    unsigned blockTotal = sh_total;

    if (t == 0)
        atomicExch(&g_scanState[blk], ((unsigned long long)blockTotal << 32) | 1ULL);
    if (t < 32) {
        unsigned excl = 0;
        int idx = blk - 1;
        while (idx >= 0) {
            int look = idx - t;
            unsigned long long s;
            unsigned flag;
            do {
                s = (look >= 0) ? *(volatile unsigned long long*)&g_scanState[look]
                                : 3ULL;
                flag = (unsigned)s;
            } while (__any_sync(0xffffffffu, flag == 0));
            unsigned val = (unsigned)(s >> 32);
            unsigned inclMask = __ballot_sync(0xffffffffu, look >= 0 && flag == 2);
            unsigned contrib;
            if (inclMask) {
                int fi = __ffs(inclMask) - 1;
                contrib = (t <= (unsigned)fi && look >= 0) ? val : 0;
            } else {
                contrib = (look >= 0) ? val : 0;
            }
#pragma unroll
            for (int o = 16; o; o >>= 1) contrib += __shfl_down_sync(0xffffffffu, contrib, o);
            excl += __shfl_sync(0xffffffffu, contrib, 0);
            if (inclMask) break;
            idx -= 32;
        }
        if (t == 0) {
            atomicExch(&g_scanState[blk],
                       ((unsigned long long)(excl + blockTotal) << 32) | 2ULL);
            sh_excl = excl;
            if (blk == NBLOCKS_SCAN - 1) g_numUnique = excl + blockTotal;
        }
    }
    __syncthreads();

    unsigned base = sh_excl + ws[t >> 5] + (inc - local);
    uint4 outv;
    outv.x = base;
    outv.y = base + c0;
    outv.z = outv.y + c1;
    outv.w = outv.z + c2;
    ((uint4*)g_wordPrefix)[blk * 256 + t] = outv;

    uint4 d4 = ((const uint4*)g_dup)[blk * 256 + t];
    unsigned dw[4] = {d4.x, d4.y, d4.z, d4.w};
    unsigned pw[4] = {v.x, v.y, v.z, v.w};
    unsigned bw[4] = {outv.x, outv.y, outv.z, outv.w};
    float4 z = make_float4(0.f, 0.f, 0.f, 0.f);
#pragma unroll
    for (int k = 0; k < 4; k++) {
        unsigned d = dw[k];
        while (d) {
            int b = __ffs(d) - 1;
            d &= d - 1;
            unsigned rank = bw[k] + __popc(pw[k] & ((1u << b) - 1u));
            float4* dst = out + (size_t)rank * 8;
#pragma unroll
            for (int q = 0; q < 8; q++) dst[q] = z;
        }
    }
}

// ---------------------------------------------------------------------------
// 4) scatter: 4 threads/point, 2 float4 each (R7-proven MLP=2) + padding zero
__global__ void k_scatter(const float4* __restrict__ feat,
                          float4* __restrict__ out, int n) {
    int tid = blockIdx.x * blockDim.x + threadIdx.x;
    int p = tid >> 2;    // point index
    int sub = tid & 3;   // handles quarter-rows sub and sub+4
    if (p >= n) return;
    int lane = threadIdx.x & 31;
    unsigned info = 0;
    if (sub == 0) {
        unsigned key = g_keys[p];
        unsigned w = key >> 5, b = key & 31;
        unsigned rank = g_wordPrefix[w] + __popc(g_bitmap[w] & ((1u << b) - 1u));
        unsigned isdup = (g_dup[w] >> b) & 1u;
        info = rank | (isdup << 31);
    }
    info = __shfl_sync(0xffffffffu, info, lane & ~3);
    unsigned rank = info & 0x7fffffffu;
    float4 f0 = feat[p * 8 + sub];        // two independent loads
    float4 f1 = feat[p * 8 + sub + 4];
    float4* dst = out + (size_t)rank * 8;
    if (info >> 31) {
        asm volatile("red.global.add.v4.f32 [%0], {%1,%2,%3,%4};"
                     :: "l"((float*)(dst + sub)), "f"(f0.x), "f"(f0.y), "f"(f0.z), "f"(f0.w)
                     : "memory");
        asm volatile("red.global.add.v4.f32 [%0], {%1,%2,%3,%4};"
                     :: "l"((float*)(dst + sub + 4)), "f"(f1.x), "f"(f1.y), "f"(f1.z), "f"(f1.w)
                     : "memory");
    } else {
        dst[sub] = f0;                    // two independent stores
        dst[sub + 4] = f1;
    }

    // padding rows [numUnique, n): never touched by scatter, safe to zero here
    unsigned nu = g_numUnique;
    unsigned row = nu + (unsigned)p;
    if (row < (unsigned)n) {
        float4 z = make_float4(0.f, 0.f, 0.f, 0.f);
        out[(size_t)row * 8 + sub] = z;
        out[(size_t)row * 8 + sub + 4] = z;
    }
}

// ---------------------------------------------------------------------------
extern "C" void kernel_launch(void* const* d_in, const int* in_sizes, int n_in,
                              void* d_out, int out_size) {
    const int4*   coords = (const int4*)d_in[0];
    const float4* feat   = (const float4*)d_in[1];
    float4*       out    = (float4*)d_out;
    int n = in_sizes[0] / 4;

    int initThreads = 2 * (NWORDS / 4) + NBLOCKS_SCAN / 2;
    k_init<<<(initThreads + 255) / 256, 256>>>();
    k_build<<<(n + 255) / 256, 256>>>(coords, n);
    k_scan_fused<<<NBLOCKS_SCAN, 256>>>(out);
    k_scatter<<<(n * 4 + 255) / 256, 256>>>(feat, out, n);
}

// round 9
// speedup vs baseline: 1.0366x; 1.0366x over previous
#include <cuda_runtime.h>
#include <cuda_bf16.h>
#include <cstdint>

// Problem constants (fixed by the reference: S=64, C=32)
#define SPATIAL 64
#define KEY_SPACE (SPATIAL * SPATIAL * SPATIAL * SPATIAL)  // 16,777,216
#define NWORDS (KEY_SPACE / 32)                            // 524,288
#define NBLOCKS_SCAN 512                                   // NWORDS / 1024
#define MAXN (1 << 21)

// Scratch (device globals — zero at module load; every call restores zeros,
// so every graph replay observes identical initial state).
__device__ unsigned g_bitmap[NWORDS];      // presence bits (restored by scan)
__device__ unsigned g_dup[NWORDS];         // dup bits      (restored by scan)
__device__ uint4    g_packed[NWORDS];      // {present, dup, prefix, 0} for scatter
__device__ unsigned long long g_scanState[NBLOCKS_SCAN];  // zeroed by build
__device__ unsigned g_keys[MAXN];
__device__ unsigned g_numUnique;

// ---------------------------------------------------------------------------
// 1) presence + dup bitmaps, key cache; first 512 threads zero scanState
__global__ void k_build(const int4* __restrict__ coords, int n) {
    int i = blockIdx.x * blockDim.x + threadIdx.x;
    if (i < NBLOCKS_SCAN) g_scanState[i] = 0ULL;  // consumed only by next launch
    if (i >= n) return;
    int4 c = coords[i];
    unsigned key = ((unsigned)((c.x * SPATIAL + c.y) * SPATIAL + c.z)) * SPATIAL + (unsigned)c.w;
    g_keys[i] = key;
    unsigned bit = 1u << (key & 31);
    unsigned old = atomicOr(&g_bitmap[key >> 5], bit);
    if (old & bit) atomicOr(&g_dup[key >> 5], bit);
}

// ---------------------------------------------------------------------------
// 2) single-pass scan (decoupled lookback) -> packed table + dup-row zeroing.
//    Restores g_bitmap / g_dup to zero for the next replay.
__global__ void __launch_bounds__(256) k_scan_fused(float4* __restrict__ out) {
    int blk = blockIdx.x, t = threadIdx.x;
    int gw4 = blk * 256 + t;
    uint4 v  = ((const uint4*)g_bitmap)[gw4];
    uint4 d4 = ((const uint4*)g_dup)[gw4];
    unsigned c0 = __popc(v.x), c1 = __popc(v.y), c2 = __popc(v.z), c3 = __popc(v.w);
    unsigned local = c0 + c1 + c2 + c3;

    // restore zeros (scatter reads only g_packed / g_keys)
    uint4 z4 = make_uint4(0, 0, 0, 0);
    ((uint4*)g_bitmap)[gw4] = z4;
    ((uint4*)g_dup)[gw4] = z4;

    // intra-warp inclusive scan
    unsigned inc = local;
#pragma unroll
    for (int o = 1; o < 32; o <<= 1) {
        unsigned nv = __shfl_up_sync(0xffffffffu, inc, o);
        if ((t & 31) >= o) inc += nv;
    }
    __shared__ unsigned ws[8];
    __shared__ unsigned sh_total, sh_excl;
    if ((t & 31) == 31) ws[t >> 5] = inc;
    __syncthreads();
    if (t < 8) {
        unsigned x = ws[t], xi = x;
#pragma unroll
        for (int o = 1; o < 8; o <<= 1) {
            unsigned nv = __shfl_up_sync(0xffu, xi, o);
            if (t >= o) xi += nv;
        }
        ws[t] = xi - x;
        if (t == 7) sh_total = xi;
    }
    __syncthreads();
    unsigned blockTotal = sh_total;

    // publish partial, then decoupled lookback (warp 0)
    if (t == 0)
        atomicExch(&g_scanState[blk], ((unsigned long long)blockTotal << 32) | 1ULL);
    if (t < 32) {
        unsigned excl = 0;
        int idx = blk - 1;
        while (idx >= 0) {
            int look = idx - t;
            unsigned long long s;
            unsigned flag;
            do {
                s = (look >= 0) ? *(volatile unsigned long long*)&g_scanState[look]
                                : 3ULL;
                flag = (unsigned)s;
            } while (__any_sync(0xffffffffu, flag == 0));
            unsigned val = (unsigned)(s >> 32);
            unsigned inclMask = __ballot_sync(0xffffffffu, look >= 0 && flag == 2);
            unsigned contrib;
            if (inclMask) {
                int fi = __ffs(inclMask) - 1;
                contrib = (t <= (unsigned)fi && look >= 0) ? val : 0;
            } else {
                contrib = (look >= 0) ? val : 0;
            }
#pragma unroll
            for (int o = 16; o; o >>= 1) contrib += __shfl_down_sync(0xffffffffu, contrib, o);
            excl += __shfl_sync(0xffffffffu, contrib, 0);
            if (inclMask) break;
            idx -= 32;
        }
        if (t == 0) {
            atomicExch(&g_scanState[blk],
                       ((unsigned long long)(excl + blockTotal) << 32) | 2ULL);
            sh_excl = excl;
            if (blk == NBLOCKS_SCAN - 1) g_numUnique = excl + blockTotal;
        }
    }
    __syncthreads();

    unsigned base = sh_excl + ws[t >> 5] + (inc - local);
    unsigned pw[4] = {v.x, v.y, v.z, v.w};
    unsigned dw[4] = {d4.x, d4.y, d4.z, d4.w};
    unsigned bw[4];
    bw[0] = base;
    bw[1] = base + c0;
    bw[2] = bw[1] + c1;
    bw[3] = bw[2] + c2;
    float4 z = make_float4(0.f, 0.f, 0.f, 0.f);
#pragma unroll
    for (int k = 0; k < 4; k++) {
        g_packed[gw4 * 4 + k] = make_uint4(pw[k], dw[k], bw[k], 0u);
        unsigned d = dw[k];
        while (d) {
            int b = __ffs(d) - 1;
            d &= d - 1;
            unsigned rank = bw[k] + __popc(pw[k] & ((1u << b) - 1u));
            float4* dst = out + (size_t)rank * 8;
#pragma unroll
            for (int q = 0; q < 8; q++) dst[q] = z;
        }
    }
}

// ---------------------------------------------------------------------------
// 3) scatter: 4 threads/point, 2 float4 each; packed-table lookup; pad zero
__global__ void k_scatter(const float4* __restrict__ feat,
                          float4* __restrict__ out, int n) {
    int tid = blockIdx.x * blockDim.x + threadIdx.x;
    int p = tid >> 2;    // point index
    int sub = tid & 3;   // handles quarter-rows sub and sub+4
    if (p >= n) return;
    int lane = threadIdx.x & 31;
    unsigned info = 0;
    if (sub == 0) {
        unsigned key = g_keys[p];
        uint4 pk = g_packed[key >> 5];      // single 16B L2 lookup
        unsigned b = key & 31;
        unsigned rank = pk.z + __popc(pk.x & ((1u << b) - 1u));
        unsigned isdup = (pk.y >> b) & 1u;
        info = rank | (isdup << 31);
    }
    info = __shfl_sync(0xffffffffu, info, lane & ~3);
    unsigned rank = info & 0x7fffffffu;
    float4 f0 = feat[p * 8 + sub];
    float4 f1 = feat[p * 8 + sub + 4];
    float4* dst = out + (size_t)rank * 8;
    if (info >> 31) {
        asm volatile("red.global.add.v4.f32 [%0], {%1,%2,%3,%4};"
                     :: "l"((float*)(dst + sub)), "f"(f0.x), "f"(f0.y), "f"(f0.z), "f"(f0.w)
                     : "memory");
        asm volatile("red.global.add.v4.f32 [%0], {%1,%2,%3,%4};"
                     :: "l"((float*)(dst + sub + 4)), "f"(f1.x), "f"(f1.y), "f"(f1.z), "f"(f1.w)
                     : "memory");
    } else {
        dst[sub] = f0;
        dst[sub + 4] = f1;
    }

    // padding rows [numUnique, n): never touched by scatter, safe to zero here
    unsigned nu = g_numUnique;
    unsigned row = nu + (unsigned)p;
    if (row < (unsigned)n) {
        float4 z = make_float4(0.f, 0.f, 0.f, 0.f);
        out[(size_t)row * 8 + sub] = z;
        out[(size_t)row * 8 + sub + 4] = z;
    }
}

// ---------------------------------------------------------------------------
extern "C" void kernel_launch(void* const* d_in, const int* in_sizes, int n_in,
                              void* d_out, int out_size) {
    const int4*   coords = (const int4*)d_in[0];
    const float4* feat   = (const float4*)d_in[1];
    float4*       out    = (float4*)d_out;
    int n = in_sizes[0] / 4;

    k_build<<<(n + 255) / 256, 256>>>(coords, n);
    k_scan_fused<<<NBLOCKS_SCAN, 256>>>(out);
    k_scatter<<<(n * 4 + 255) / 256, 256>>>(feat, out, n);
}